// round 6
// baseline (speedup 1.0000x reference)
#include <cuda_runtime.h>
#include <cuda_bf16.h>
#include <math.h>

// Problem constants
#define BATCH 4
#define SEQ   2048
#define EMB   1024
#define NH    16
#define HD    64
#define WIN   512

// Scratch (device globals; allocation is forbidden)
__device__ float g_q[(size_t)BATCH * NH * SEQ * HD];   // [B,H,S,D]
__device__ float g_k[(size_t)BATCH * NH * SEQ * HD];
__device__ float g_v[(size_t)BATCH * NH * SEQ * HD];
__device__ float g_o[(size_t)BATCH * SEQ * EMB];       // [B,S,E]

// ---------------------------------------------------------------------------
// SGEMM (NT): C[M,N] = A[M,K] * B[N,K]^T, K = 1024, tiles 128x128x16,
// 256 threads, 8x8 per-thread microtile.
// ---------------------------------------------------------------------------
#define BM 128
#define BN 128
#define BKK 16

// GEMM1: qkv projection with scatter into g_q/g_k/g_v ([B,H,S,D] layout)
__global__ __launch_bounds__(256)
void qkv_gemm(const float* __restrict__ A,    // x   [8192, 1024]
              const float* __restrict__ B)    // w_in [3072, 1024]
{
    __shared__ float As[BKK][BM];
    __shared__ float Bs[BKK][BN];

    const int K = EMB;
    const int tid = threadIdx.x;
    const int m0 = blockIdx.y * BM;
    const int n0 = blockIdx.x * BN;
    const int tx = tid & 15;
    const int ty = tid >> 4;
    const int tm = ty * 8;
    const int tn = tx * 8;

    float acc[8][8];
#pragma unroll
    for (int i = 0; i < 8; i++)
#pragma unroll
        for (int j = 0; j < 8; j++) acc[i][j] = 0.f;

    const float* Ag = A + (size_t)m0 * K;
    const float* Bg = B + (size_t)n0 * K;

    for (int k0 = 0; k0 < K; k0 += BKK) {
#pragma unroll
        for (int i = 0; i < 2; i++) {
            int f = tid + i * 256;
            int r = f >> 2;
            int c = (f & 3) << 2;
            float4 av = *(const float4*)(Ag + (size_t)r * K + k0 + c);
            As[c + 0][r] = av.x; As[c + 1][r] = av.y;
            As[c + 2][r] = av.z; As[c + 3][r] = av.w;
            float4 bv = *(const float4*)(Bg + (size_t)r * K + k0 + c);
            Bs[c + 0][r] = bv.x; Bs[c + 1][r] = bv.y;
            Bs[c + 2][r] = bv.z; Bs[c + 3][r] = bv.w;
        }
        __syncthreads();
#pragma unroll
        for (int kk = 0; kk < BKK; kk++) {
            float a[8], b[8];
            *(float4*)&a[0] = *(const float4*)&As[kk][tm];
            *(float4*)&a[4] = *(const float4*)&As[kk][tm + 4];
            *(float4*)&b[0] = *(const float4*)&Bs[kk][tn];
            *(float4*)&b[4] = *(const float4*)&Bs[kk][tn + 4];
#pragma unroll
            for (int i = 0; i < 8; i++)
#pragma unroll
                for (int j = 0; j < 8; j++)
                    acc[i][j] = fmaf(a[i], b[j], acc[i][j]);
        }
        __syncthreads();
    }

    // Scatter epilogue: f = n0+tn..+7 lies in one part (q/k/v) and one head.
    int f0 = n0 + tn;
    int part = f0 >> 10;            // 0=q, 1=k, 2=v
    int e2 = f0 & 1023;
    int hh = e2 >> 6;
    int d0 = e2 & 63;
    float* base = (part == 0) ? g_q : (part == 1) ? g_k : g_v;

#pragma unroll
    for (int i = 0; i < 8; i++) {
        int m = m0 + tm + i;
        int bb = m >> 11;           // / SEQ
        int ss = m & 2047;
        size_t off = ((((size_t)bb * NH + hh) * SEQ) + ss) * HD + d0;
        float4 v0 = make_float4(acc[i][0], acc[i][1], acc[i][2], acc[i][3]);
        float4 v1 = make_float4(acc[i][4], acc[i][5], acc[i][6], acc[i][7]);
        *(float4*)(base + off) = v0;
        *(float4*)(base + off + 4) = v1;
    }
}

// GEMM2: output projection, plain row-major C
__global__ __launch_bounds__(256)
void out_gemm(const float* __restrict__ A,    // g_o   [8192, 1024]
              const float* __restrict__ B,    // w_out [1024, 1024]
              float* __restrict__ C)          // out   [8192, 1024]
{
    __shared__ float As[BKK][BM];
    __shared__ float Bs[BKK][BN];

    const int K = EMB;
    const int tid = threadIdx.x;
    const int m0 = blockIdx.y * BM;
    const int n0 = blockIdx.x * BN;
    const int tx = tid & 15;
    const int ty = tid >> 4;
    const int tm = ty * 8;
    const int tn = tx * 8;

    float acc[8][8];
#pragma unroll
    for (int i = 0; i < 8; i++)
#pragma unroll
        for (int j = 0; j < 8; j++) acc[i][j] = 0.f;

    const float* Ag = A + (size_t)m0 * K;
    const float* Bg = B + (size_t)n0 * K;

    for (int k0 = 0; k0 < K; k0 += BKK) {
#pragma unroll
        for (int i = 0; i < 2; i++) {
            int f = tid + i * 256;
            int r = f >> 2;
            int c = (f & 3) << 2;
            float4 av = *(const float4*)(Ag + (size_t)r * K + k0 + c);
            As[c + 0][r] = av.x; As[c + 1][r] = av.y;
            As[c + 2][r] = av.z; As[c + 3][r] = av.w;
            float4 bv = *(const float4*)(Bg + (size_t)r * K + k0 + c);
            Bs[c + 0][r] = bv.x; Bs[c + 1][r] = bv.y;
            Bs[c + 2][r] = bv.z; Bs[c + 3][r] = bv.w;
        }
        __syncthreads();
#pragma unroll
        for (int kk = 0; kk < BKK; kk++) {
            float a[8], b[8];
            *(float4*)&a[0] = *(const float4*)&As[kk][tm];
            *(float4*)&a[4] = *(const float4*)&As[kk][tm + 4];
            *(float4*)&b[0] = *(const float4*)&Bs[kk][tn];
            *(float4*)&b[4] = *(const float4*)&Bs[kk][tn + 4];
#pragma unroll
            for (int i = 0; i < 8; i++)
#pragma unroll
                for (int j = 0; j < 8; j++)
                    acc[i][j] = fmaf(a[i], b[j], acc[i][j]);
        }
        __syncthreads();
    }

#pragma unroll
    for (int i = 0; i < 8; i++) {
        int m = m0 + tm + i;
        float* crow = C + (size_t)m * EMB + n0 + tn;
        float4 v0 = make_float4(acc[i][0], acc[i][1], acc[i][2], acc[i][3]);
        float4 v1 = make_float4(acc[i][4], acc[i][5], acc[i][6], acc[i][7]);
        *(float4*)(crow) = v0;
        *(float4*)(crow + 4) = v1;
    }
}

// ---------------------------------------------------------------------------
// Sliding-window attention with ALiBi.
// Grid: (S/128, H, B). 128 threads, one query per thread.
// Softmax shift is the analytic bound m = slope * min(qi, WIN): no online
// max / no accumulator rescaling needed (shift cancels in the final divide;
// underflowed terms are exactly the ones the reference makes negligible).
// ---------------------------------------------------------------------------
#define QT 128
#define CK 64

__global__ __launch_bounds__(128)
void attn_kernel()
{
    __shared__ float4 Ks[CK * 16];
    __shared__ float4 Vs[CK * 16];

    const int b = blockIdx.z;
    const int h = blockIdx.y;
    const int qs = blockIdx.x * QT;
    const int t = threadIdx.x;
    const int qi = qs + t;

    const size_t head_off = (((size_t)b * NH + h) * SEQ) * HD;
    const float* qrow = g_q + head_off + (size_t)qi * HD;
    const float* kbase = g_k + head_off;
    const float* vbase = g_v + head_off;

    float4 q[16];
#pragma unroll
    for (int d4 = 0; d4 < 16; d4++) q[d4] = ((const float4*)qrow)[d4];

    const float slope = exp2f(-(float)(h + 1) * 0.5f);
    const int dmin = (qi < WIN) ? qi : WIN;

    float4 acc[16];
#pragma unroll
    for (int d4 = 0; d4 < 16; d4++) acc[d4] = make_float4(0.f, 0.f, 0.f, 0.f);
    float l = 0.f;

    const int lo = (qs >= WIN) ? (qs - WIN) : 0;

    for (int ck = lo; ck < qs + QT; ck += CK) {
        __syncthreads();
        const float4* ksrc = (const float4*)(kbase + (size_t)ck * HD);
        const float4* vsrc = (const float4*)(vbase + (size_t)ck * HD);
#pragma unroll
        for (int i = 0; i < 8; i++) {
            Ks[t + i * 128] = ksrc[t + i * 128];
            Vs[t + i * 128] = vsrc[t + i * 128];
        }
        __syncthreads();

        // exponent offset: slope*(qi - kv) - slope*dmin, computed on small ints
        const float cc = slope * (float)(qi - dmin - ck);

#pragma unroll 1
        for (int j = 0; j < CK; j++) {
            int kv = ck + j;
            if (kv > qi || kv < qi - WIN) continue;

            float s0 = 0.f, s1 = 0.f, s2 = 0.f, s3 = 0.f;
#pragma unroll
            for (int d4 = 0; d4 < 16; d4 += 4) {
                float4 ka = Ks[j * 16 + d4 + 0];
                s0 = fmaf(q[d4 + 0].x, ka.x, s0); s0 = fmaf(q[d4 + 0].y, ka.y, s0);
                s0 = fmaf(q[d4 + 0].z, ka.z, s0); s0 = fmaf(q[d4 + 0].w, ka.w, s0);
                float4 kb = Ks[j * 16 + d4 + 1];
                s1 = fmaf(q[d4 + 1].x, kb.x, s1); s1 = fmaf(q[d4 + 1].y, kb.y, s1);
                s1 = fmaf(q[d4 + 1].z, kb.z, s1); s1 = fmaf(q[d4 + 1].w, kb.w, s1);
                float4 kc = Ks[j * 16 + d4 + 2];
                s2 = fmaf(q[d4 + 2].x, kc.x, s2); s2 = fmaf(q[d4 + 2].y, kc.y, s2);
                s2 = fmaf(q[d4 + 2].z, kc.z, s2); s2 = fmaf(q[d4 + 2].w, kc.w, s2);
                float4 kd = Ks[j * 16 + d4 + 3];
                s3 = fmaf(q[d4 + 3].x, kd.x, s3); s3 = fmaf(q[d4 + 3].y, kd.y, s3);
                s3 = fmaf(q[d4 + 3].z, kd.z, s3); s3 = fmaf(q[d4 + 3].w, kd.w, s3);
            }
            float s = (s0 + s1) + (s2 + s3);
            float arg = fmaf(s, 0.125f, fmaf(-slope, (float)j, cc));
            float p = __expf(arg);
            l += p;
#pragma unroll
            for (int d4 = 0; d4 < 16; d4++) {
                float4 vv = Vs[j * 16 + d4];
                acc[d4].x = fmaf(p, vv.x, acc[d4].x);
                acc[d4].y = fmaf(p, vv.y, acc[d4].y);
                acc[d4].z = fmaf(p, vv.z, acc[d4].z);
                acc[d4].w = fmaf(p, vv.w, acc[d4].w);
            }
        }
    }

    const float inv = 1.f / l;
    float* orow = g_o + ((size_t)b * SEQ + qi) * EMB + h * HD;
#pragma unroll
    for (int d4 = 0; d4 < 16; d4++) {
        float4 r = acc[d4];
        r.x *= inv; r.y *= inv; r.z *= inv; r.w *= inv;
        ((float4*)orow)[d4] = r;
    }
}

// ---------------------------------------------------------------------------
extern "C" void kernel_launch(void* const* d_in, const int* in_sizes, int n_in,
                              void* d_out, int out_size)
{
    const float* x     = (const float*)d_in[0];   // [B,S,E]
    const float* w_in  = (const float*)d_in[1];   // [3E,E]
    const float* w_out = (const float*)d_in[2];   // [E,E]
    float* out = (float*)d_out;                   // [B,S,E]

    float* go_ptr = nullptr;
    cudaGetSymbolAddress((void**)&go_ptr, g_o);

    // 1) QKV projection: [8192,3072] scattered to q/k/v [B,H,S,D]
    {
        dim3 grid(3 * EMB / BN, (BATCH * SEQ) / BM);
        qkv_gemm<<<grid, 256>>>(x, w_in);
    }
    // 2) Sliding-window attention -> g_o [B,S,E]
    {
        dim3 grid(SEQ / QT, NH, BATCH);
        attn_kernel<<<grid, 128>>>();
    }
    // 3) Output projection
    {
        dim3 grid(EMB / BN, (BATCH * SEQ) / BM);
        out_gemm<<<grid, 256>>>(go_ptr, w_out, out);
    }
}

// round 10
// speedup vs baseline: 1.6265x; 1.6265x over previous
#include <cuda_runtime.h>
#include <cuda_bf16.h>
#include <math.h>
#include <stdint.h>

// Problem constants
#define BATCH 4
#define SEQ   2048
#define EMB   1024
#define NH    16
#define HD    64
#define WIN   512

// Scratch (device globals; allocation is forbidden)
__device__ float g_q[(size_t)BATCH * NH * SEQ * HD];   // [B,H,S,D]
__device__ float g_k[(size_t)BATCH * NH * SEQ * HD];
__device__ float g_v[(size_t)BATCH * NH * SEQ * HD];
__device__ float g_o[(size_t)BATCH * SEQ * EMB];       // [B,S,E]

// ---------------------------------------------------------------------------
// TF32 tensor-core GEMM (NT): C[M,N] = A[M,K] * B[N,K]^T, K=1024.
// Block tile 128x128, K-tile 16, 256 threads = 8 warps (4M x 2N),
// warp tile 32x64 via mma.sync m16n8k8 tf32 (2 m-tiles x 8 n-tiles).
// ---------------------------------------------------------------------------
#define BM 128
#define BN 128
#define BKK 16
#define SPAD 132   // padded smem row stride (words)

__device__ __forceinline__ uint32_t f2tf(float x) {
    uint32_t r;
    asm("cvt.rna.tf32.f32 %0, %1;" : "=r"(r) : "f"(x));
    return r;
}

#define MMA_TF32(c, a, b0_, b1_)                                            \
    asm volatile(                                                           \
        "mma.sync.aligned.m16n8k8.row.col.f32.tf32.tf32.f32 "               \
        "{%0,%1,%2,%3}, {%4,%5,%6,%7}, {%8,%9}, {%0,%1,%2,%3};"            \
        : "+f"((c)[0]), "+f"((c)[1]), "+f"((c)[2]), "+f"((c)[3])            \
        : "r"((a)[0]), "r"((a)[1]), "r"((a)[2]), "r"((a)[3]),               \
          "r"(b0_), "r"(b1_))

// Shared mainloop: computes warp's 32x64 accumulators.
// acc layout: acc[mt][nt][4] fragments.
__device__ __forceinline__ void gemm_mainloop(
    const float* __restrict__ Ag, const float* __restrict__ Bg,
    uint32_t (*As)[SPAD], uint32_t (*Bs)[SPAD],
    float acc[2][8][4],
    int tid, int warpM, int warpN, int g, int tg)
{
    const int K = EMB;
    for (int k0 = 0; k0 < K; k0 += BKK) {
#pragma unroll
        for (int i = 0; i < 2; i++) {
            int f = tid + i * 256;
            int r = f >> 2;
            int c = (f & 3) << 2;
            float4 av = *(const float4*)(Ag + (size_t)r * K + k0 + c);
            As[c + 0][r] = f2tf(av.x); As[c + 1][r] = f2tf(av.y);
            As[c + 2][r] = f2tf(av.z); As[c + 3][r] = f2tf(av.w);
            float4 bv = *(const float4*)(Bg + (size_t)r * K + k0 + c);
            Bs[c + 0][r] = f2tf(bv.x); Bs[c + 1][r] = f2tf(bv.y);
            Bs[c + 2][r] = f2tf(bv.z); Bs[c + 3][r] = f2tf(bv.w);
        }
        __syncthreads();

#pragma unroll
        for (int ks = 0; ks < 2; ks++) {
            const int kb = ks * 8;
            uint32_t a[2][4];
#pragma unroll
            for (int mt = 0; mt < 2; mt++) {
                int row = warpM * 32 + mt * 16 + g;
                a[mt][0] = As[kb + tg][row];
                a[mt][1] = As[kb + tg][row + 8];
                a[mt][2] = As[kb + tg + 4][row];
                a[mt][3] = As[kb + tg + 4][row + 8];
            }
#pragma unroll
            for (int nt = 0; nt < 8; nt++) {
                int col = warpN * 64 + nt * 8 + g;
                uint32_t b0 = Bs[kb + tg][col];
                uint32_t b1 = Bs[kb + tg + 4][col];
                MMA_TF32(acc[0][nt], a[0], b0, b1);
                MMA_TF32(acc[1][nt], a[1], b0, b1);
            }
        }
        __syncthreads();
    }
}

// GEMM1: qkv projection with scatter into g_q/g_k/g_v ([B,H,S,D] layout)
__global__ __launch_bounds__(256)
void qkv_gemm(const float* __restrict__ A,    // x    [8192, 1024]
              const float* __restrict__ B)    // w_in [3072, 1024]
{
    __shared__ uint32_t As[BKK][SPAD];
    __shared__ uint32_t Bs[BKK][SPAD];

    const int tid = threadIdx.x;
    const int m0 = blockIdx.y * BM;
    const int n0 = blockIdx.x * BN;
    const int warp = tid >> 5;
    const int warpM = warp >> 1;
    const int warpN = warp & 1;
    const int lane = tid & 31;
    const int g = lane >> 2;
    const int tg = lane & 3;

    float acc[2][8][4];
#pragma unroll
    for (int mt = 0; mt < 2; mt++)
#pragma unroll
        for (int nt = 0; nt < 8; nt++)
#pragma unroll
            for (int j = 0; j < 4; j++) acc[mt][nt][j] = 0.f;

    gemm_mainloop(A + (size_t)m0 * EMB, B + (size_t)n0 * EMB,
                  As, Bs, acc, tid, warpM, warpN, g, tg);

    // Scatter epilogue into q/k/v [B,H,S,D]
#pragma unroll
    for (int nt = 0; nt < 8; nt++) {
        int f = n0 + warpN * 64 + nt * 8 + 2 * tg;
        int part = f >> 10;            // 0=q, 1=k, 2=v
        int e2 = f & 1023;
        int hh = e2 >> 6;
        int d0 = e2 & 63;
        float* base = (part == 0) ? g_q : (part == 1) ? g_k : g_v;
#pragma unroll
        for (int mt = 0; mt < 2; mt++) {
            int r0 = m0 + warpM * 32 + mt * 16 + g;
            // row r0
            {
                int bb = r0 >> 11;
                int ss = r0 & 2047;
                size_t off = ((((size_t)bb * NH + hh) * SEQ) + ss) * HD + d0;
                *(float2*)(base + off) = make_float2(acc[mt][nt][0], acc[mt][nt][1]);
            }
            // row r0 + 8
            {
                int r1 = r0 + 8;
                int bb = r1 >> 11;
                int ss = r1 & 2047;
                size_t off = ((((size_t)bb * NH + hh) * SEQ) + ss) * HD + d0;
                *(float2*)(base + off) = make_float2(acc[mt][nt][2], acc[mt][nt][3]);
            }
        }
    }
}

// GEMM2: output projection, plain row-major C
__global__ __launch_bounds__(256)
void out_gemm(const float* __restrict__ A,    // g_o   [8192, 1024]
              const float* __restrict__ B,    // w_out [1024, 1024]
              float* __restrict__ C)          // out   [8192, 1024]
{
    __shared__ uint32_t As[BKK][SPAD];
    __shared__ uint32_t Bs[BKK][SPAD];

    const int tid = threadIdx.x;
    const int m0 = blockIdx.y * BM;
    const int n0 = blockIdx.x * BN;
    const int warp = tid >> 5;
    const int warpM = warp >> 1;
    const int warpN = warp & 1;
    const int lane = tid & 31;
    const int g = lane >> 2;
    const int tg = lane & 3;

    float acc[2][8][4];
#pragma unroll
    for (int mt = 0; mt < 2; mt++)
#pragma unroll
        for (int nt = 0; nt < 8; nt++)
#pragma unroll
            for (int j = 0; j < 4; j++) acc[mt][nt][j] = 0.f;

    gemm_mainloop(A + (size_t)m0 * EMB, B + (size_t)n0 * EMB,
                  As, Bs, acc, tid, warpM, warpN, g, tg);

#pragma unroll
    for (int nt = 0; nt < 8; nt++) {
        int f = n0 + warpN * 64 + nt * 8 + 2 * tg;
#pragma unroll
        for (int mt = 0; mt < 2; mt++) {
            int r0 = m0 + warpM * 32 + mt * 16 + g;
            *(float2*)(C + (size_t)r0 * EMB + f) =
                make_float2(acc[mt][nt][0], acc[mt][nt][1]);
            *(float2*)(C + (size_t)(r0 + 8) * EMB + f) =
                make_float2(acc[mt][nt][2], acc[mt][nt][3]);
        }
    }
}

// ---------------------------------------------------------------------------
// Sliding-window attention with ALiBi (unchanged from R5 passing version).
// Grid: (S/128, H, B). 128 threads, one query per thread.
// Softmax shift is the analytic bound m = slope * min(qi, WIN): no online
// max / no accumulator rescaling needed (shift cancels in the final divide;
// underflowed terms are exactly the ones the reference makes negligible).
// ---------------------------------------------------------------------------
#define QT 128
#define CK 64

__global__ __launch_bounds__(128)
void attn_kernel()
{
    __shared__ float4 Ks[CK * 16];
    __shared__ float4 Vs[CK * 16];

    const int b = blockIdx.z;
    const int h = blockIdx.y;
    const int qs = blockIdx.x * QT;
    const int t = threadIdx.x;
    const int qi = qs + t;

    const size_t head_off = (((size_t)b * NH + h) * SEQ) * HD;
    const float* qrow = g_q + head_off + (size_t)qi * HD;
    const float* kbase = g_k + head_off;
    const float* vbase = g_v + head_off;

    float4 q[16];
#pragma unroll
    for (int d4 = 0; d4 < 16; d4++) q[d4] = ((const float4*)qrow)[d4];

    const float slope = exp2f(-(float)(h + 1) * 0.5f);
    const int dmin = (qi < WIN) ? qi : WIN;

    float4 acc[16];
#pragma unroll
    for (int d4 = 0; d4 < 16; d4++) acc[d4] = make_float4(0.f, 0.f, 0.f, 0.f);
    float l = 0.f;

    const int lo = (qs >= WIN) ? (qs - WIN) : 0;

    for (int ck = lo; ck < qs + QT; ck += CK) {
        __syncthreads();
        const float4* ksrc = (const float4*)(kbase + (size_t)ck * HD);
        const float4* vsrc = (const float4*)(vbase + (size_t)ck * HD);
#pragma unroll
        for (int i = 0; i < 8; i++) {
            Ks[t + i * 128] = ksrc[t + i * 128];
            Vs[t + i * 128] = vsrc[t + i * 128];
        }
        __syncthreads();

        // exponent offset: slope*(qi - kv) - slope*dmin, computed on small ints
        const float cc = slope * (float)(qi - dmin - ck);

#pragma unroll 1
        for (int j = 0; j < CK; j++) {
            int kv = ck + j;
            if (kv > qi || kv < qi - WIN) continue;

            float s0 = 0.f, s1 = 0.f, s2 = 0.f, s3 = 0.f;
#pragma unroll
            for (int d4 = 0; d4 < 16; d4 += 4) {
                float4 ka = Ks[j * 16 + d4 + 0];
                s0 = fmaf(q[d4 + 0].x, ka.x, s0); s0 = fmaf(q[d4 + 0].y, ka.y, s0);
                s0 = fmaf(q[d4 + 0].z, ka.z, s0); s0 = fmaf(q[d4 + 0].w, ka.w, s0);
                float4 kb = Ks[j * 16 + d4 + 1];
                s1 = fmaf(q[d4 + 1].x, kb.x, s1); s1 = fmaf(q[d4 + 1].y, kb.y, s1);
                s1 = fmaf(q[d4 + 1].z, kb.z, s1); s1 = fmaf(q[d4 + 1].w, kb.w, s1);
                float4 kc = Ks[j * 16 + d4 + 2];
                s2 = fmaf(q[d4 + 2].x, kc.x, s2); s2 = fmaf(q[d4 + 2].y, kc.y, s2);
                s2 = fmaf(q[d4 + 2].z, kc.z, s2); s2 = fmaf(q[d4 + 2].w, kc.w, s2);
                float4 kd = Ks[j * 16 + d4 + 3];
                s3 = fmaf(q[d4 + 3].x, kd.x, s3); s3 = fmaf(q[d4 + 3].y, kd.y, s3);
                s3 = fmaf(q[d4 + 3].z, kd.z, s3); s3 = fmaf(q[d4 + 3].w, kd.w, s3);
            }
            float s = (s0 + s1) + (s2 + s3);
            float arg = fmaf(s, 0.125f, fmaf(-slope, (float)j, cc));
            float p = __expf(arg);
            l += p;
#pragma unroll
            for (int d4 = 0; d4 < 16; d4++) {
                float4 vv = Vs[j * 16 + d4];
                acc[d4].x = fmaf(p, vv.x, acc[d4].x);
                acc[d4].y = fmaf(p, vv.y, acc[d4].y);
                acc[d4].z = fmaf(p, vv.z, acc[d4].z);
                acc[d4].w = fmaf(p, vv.w, acc[d4].w);
            }
        }
    }

    const float inv = 1.f / l;
    float* orow = g_o + ((size_t)b * SEQ + qi) * EMB + h * HD;
#pragma unroll
    for (int d4 = 0; d4 < 16; d4++) {
        float4 r = acc[d4];
        r.x *= inv; r.y *= inv; r.z *= inv; r.w *= inv;
        ((float4*)orow)[d4] = r;
    }
}

// ---------------------------------------------------------------------------
extern "C" void kernel_launch(void* const* d_in, const int* in_sizes, int n_in,
                              void* d_out, int out_size)
{
    const float* x     = (const float*)d_in[0];   // [B,S,E]
    const float* w_in  = (const float*)d_in[1];   // [3E,E]
    const float* w_out = (const float*)d_in[2];   // [E,E]
    float* out = (float*)d_out;                   // [B,S,E]

    float* go_ptr = nullptr;
    cudaGetSymbolAddress((void**)&go_ptr, g_o);

    // 1) QKV projection: [8192,3072] scattered to q/k/v [B,H,S,D]
    {
        dim3 grid(3 * EMB / BN, (BATCH * SEQ) / BM);
        qkv_gemm<<<grid, 256>>>(x, w_in);
    }
    // 2) Sliding-window attention -> g_o [B,S,E]
    {
        dim3 grid(SEQ / QT, NH, BATCH);
        attn_kernel<<<grid, 128>>>();
    }
    // 3) Output projection
    {
        dim3 grid(EMB / BN, (BATCH * SEQ) / BM);
        out_gemm<<<grid, 256>>>(go_ptr, w_out, out);
    }
}

// round 11
// speedup vs baseline: 1.7763x; 1.0921x over previous
#include <cuda_runtime.h>
#include <cuda_bf16.h>
#include <math.h>
#include <stdint.h>

// Problem constants
#define BATCH 4
#define SEQ   2048
#define EMB   1024
#define NH    16
#define HD    64
#define WIN   512

// Scratch (device globals; allocation is forbidden)
__device__ float g_q[(size_t)BATCH * NH * SEQ * HD];   // [B,H,S,D]
__device__ float g_k[(size_t)BATCH * NH * SEQ * HD];
__device__ float g_v[(size_t)BATCH * NH * SEQ * HD];
__device__ float g_o[(size_t)BATCH * SEQ * EMB];       // [B,S,E]

// ---------------------------------------------------------------------------
// TF32 tensor-core GEMM (NT): C[M,N] = A[M,K] * B[N,K]^T, K=1024.
// Block tile 128x128, K-tile 16, 256 threads = 8 warps (4M x 2N),
// warp tile 32x64 via mma.sync m16n8k8 tf32.
//
// Smem is natural [row][k] layout, stride 16 words (no pad). All smem traffic
// is 128-bit and conflict-free. The two k-slices of each k-tile use a
// permuted k-assignment (thread tg owns phys k {4tg..4tg+3}; slice 0 consumes
// {4tg,4tg+1}, slice 1 consumes {4tg+2,4tg+3}) — valid since A and B agree.
// ---------------------------------------------------------------------------
#define BM 128
#define BN 128
#define BKK 16

__device__ __forceinline__ uint32_t f2tf(float x) {
    uint32_t r;
    asm("cvt.rna.tf32.f32 %0, %1;" : "=r"(r) : "f"(x));
    return r;
}

#define MMA_TF32(c, a, b0_, b1_)                                            \
    asm volatile(                                                           \
        "mma.sync.aligned.m16n8k8.row.col.f32.tf32.tf32.f32 "               \
        "{%0,%1,%2,%3}, {%4,%5,%6,%7}, {%8,%9}, {%0,%1,%2,%3};"            \
        : "+f"((c)[0]), "+f"((c)[1]), "+f"((c)[2]), "+f"((c)[3])            \
        : "r"((a)[0]), "r"((a)[1]), "r"((a)[2]), "r"((a)[3]),               \
          "r"(b0_), "r"(b1_))

__device__ __forceinline__ uint4 cvt4(float4 v) {
    return make_uint4(f2tf(v.x), f2tf(v.y), f2tf(v.z), f2tf(v.w));
}

// Shared mainloop: computes warp's 32x64 accumulators. acc[mt][nt][4].
__device__ __forceinline__ void gemm_mainloop(
    const float* __restrict__ Ag, const float* __restrict__ Bg,
    uint32_t (*As)[BKK], uint32_t (*Bs)[BKK],
    float acc[2][8][4],
    int tid, int warpM, int warpN, int g, int tg)
{
    const int K = EMB;
    const int r = tid >> 2;          // 0..63  (rows r and r+64)
    const int c = (tid & 3) << 2;    // 0,4,8,12

    const float* Ar0 = Ag + (size_t)r * K + c;
    const float* Ar1 = Ag + (size_t)(r + 64) * K + c;
    const float* Br0 = Bg + (size_t)r * K + c;
    const float* Br1 = Bg + (size_t)(r + 64) * K + c;

    // prefetch k-tile 0
    float4 av0 = *(const float4*)(Ar0);
    float4 av1 = *(const float4*)(Ar1);
    float4 bv0 = *(const float4*)(Br0);
    float4 bv1 = *(const float4*)(Br1);

    for (int k0 = 0; k0 < K; k0 += BKK) {
        // store current tile (smem is free: first iter or post-sync)
        *(uint4*)&As[r][c]       = cvt4(av0);
        *(uint4*)&As[r + 64][c]  = cvt4(av1);
        *(uint4*)&Bs[r][c]       = cvt4(bv0);
        *(uint4*)&Bs[r + 64][c]  = cvt4(bv1);
        __syncthreads();

        // prefetch next tile while computing
        if (k0 + BKK < K) {
            av0 = *(const float4*)(Ar0 + k0 + BKK);
            av1 = *(const float4*)(Ar1 + k0 + BKK);
            bv0 = *(const float4*)(Br0 + k0 + BKK);
            bv1 = *(const float4*)(Br1 + k0 + BKK);
        }

        // A fragments for both k-slices: 4x LDS.128
        uint32_t a[2][2][4];   // [ks][mt][frag]
#pragma unroll
        for (int mt = 0; mt < 2; mt++) {
            int row = warpM * 32 + mt * 16 + g;
            uint4 va = *(const uint4*)&As[row][tg * 4];
            uint4 vb = *(const uint4*)&As[row + 8][tg * 4];
            a[0][mt][0] = va.x; a[0][mt][1] = vb.x;
            a[0][mt][2] = va.y; a[0][mt][3] = vb.y;
            a[1][mt][0] = va.z; a[1][mt][1] = vb.z;
            a[1][mt][2] = va.w; a[1][mt][3] = vb.w;
        }
        // B: 8x LDS.128, 4 MMAs each
#pragma unroll
        for (int nt = 0; nt < 8; nt++) {
            int col = warpN * 64 + nt * 8 + g;
            uint4 wv = *(const uint4*)&Bs[col][tg * 4];
            MMA_TF32(acc[0][nt], a[0][0], wv.x, wv.y);
            MMA_TF32(acc[1][nt], a[0][1], wv.x, wv.y);
            MMA_TF32(acc[0][nt], a[1][0], wv.z, wv.w);
            MMA_TF32(acc[1][nt], a[1][1], wv.z, wv.w);
        }
        __syncthreads();
    }
}

// GEMM1: qkv projection with scatter into g_q/g_k/g_v ([B,H,S,D] layout)
__global__ __launch_bounds__(256, 2)
void qkv_gemm(const float* __restrict__ A,    // x    [8192, 1024]
              const float* __restrict__ B)    // w_in [3072, 1024]
{
    __shared__ uint32_t As[BM][BKK];
    __shared__ uint32_t Bs[BN][BKK];

    const int tid = threadIdx.x;
    const int m0 = blockIdx.y * BM;
    const int n0 = blockIdx.x * BN;
    const int warp = tid >> 5;
    const int warpM = warp >> 1;
    const int warpN = warp & 1;
    const int lane = tid & 31;
    const int g = lane >> 2;
    const int tg = lane & 3;

    float acc[2][8][4];
#pragma unroll
    for (int mt = 0; mt < 2; mt++)
#pragma unroll
        for (int nt = 0; nt < 8; nt++)
#pragma unroll
            for (int j = 0; j < 4; j++) acc[mt][nt][j] = 0.f;

    gemm_mainloop(A + (size_t)m0 * EMB, B + (size_t)n0 * EMB,
                  As, Bs, acc, tid, warpM, warpN, g, tg);

    // Scatter epilogue into q/k/v [B,H,S,D]
#pragma unroll
    for (int nt = 0; nt < 8; nt++) {
        int f = n0 + warpN * 64 + nt * 8 + 2 * tg;
        int part = f >> 10;            // 0=q, 1=k, 2=v
        int e2 = f & 1023;
        int hh = e2 >> 6;
        int d0 = e2 & 63;
        float* base = (part == 0) ? g_q : (part == 1) ? g_k : g_v;
#pragma unroll
        for (int mt = 0; mt < 2; mt++) {
            int r0 = m0 + warpM * 32 + mt * 16 + g;
            {
                int bb = r0 >> 11;
                int ss = r0 & 2047;
                size_t off = ((((size_t)bb * NH + hh) * SEQ) + ss) * HD + d0;
                *(float2*)(base + off) = make_float2(acc[mt][nt][0], acc[mt][nt][1]);
            }
            {
                int r1 = r0 + 8;
                int bb = r1 >> 11;
                int ss = r1 & 2047;
                size_t off = ((((size_t)bb * NH + hh) * SEQ) + ss) * HD + d0;
                *(float2*)(base + off) = make_float2(acc[mt][nt][2], acc[mt][nt][3]);
            }
        }
    }
}

// GEMM2: output projection, plain row-major C
__global__ __launch_bounds__(256, 2)
void out_gemm(const float* __restrict__ A,    // g_o   [8192, 1024]
              const float* __restrict__ B,    // w_out [1024, 1024]
              float* __restrict__ C)          // out   [8192, 1024]
{
    __shared__ uint32_t As[BM][BKK];
    __shared__ uint32_t Bs[BN][BKK];

    const int tid = threadIdx.x;
    const int m0 = blockIdx.y * BM;
    const int n0 = blockIdx.x * BN;
    const int warp = tid >> 5;
    const int warpM = warp >> 1;
    const int warpN = warp & 1;
    const int lane = tid & 31;
    const int g = lane >> 2;
    const int tg = lane & 3;

    float acc[2][8][4];
#pragma unroll
    for (int mt = 0; mt < 2; mt++)
#pragma unroll
        for (int nt = 0; nt < 8; nt++)
#pragma unroll
            for (int j = 0; j < 4; j++) acc[mt][nt][j] = 0.f;

    gemm_mainloop(A + (size_t)m0 * EMB, B + (size_t)n0 * EMB,
                  As, Bs, acc, tid, warpM, warpN, g, tg);

#pragma unroll
    for (int nt = 0; nt < 8; nt++) {
        int f = n0 + warpN * 64 + nt * 8 + 2 * tg;
#pragma unroll
        for (int mt = 0; mt < 2; mt++) {
            int r0 = m0 + warpM * 32 + mt * 16 + g;
            *(float2*)(C + (size_t)r0 * EMB + f) =
                make_float2(acc[mt][nt][0], acc[mt][nt][1]);
            *(float2*)(C + (size_t)(r0 + 8) * EMB + f) =
                make_float2(acc[mt][nt][2], acc[mt][nt][3]);
        }
    }
}

// ---------------------------------------------------------------------------
// Sliding-window attention with ALiBi (unchanged — passing, ~735us; next
// round's target). Grid: (S/128, H, B). 128 threads, one query per thread.
// Softmax shift is the analytic bound m = slope * min(qi, WIN).
// ---------------------------------------------------------------------------
#define QT 128
#define CK 64

__global__ __launch_bounds__(128)
void attn_kernel()
{
    __shared__ float4 Ks[CK * 16];
    __shared__ float4 Vs[CK * 16];

    const int b = blockIdx.z;
    const int h = blockIdx.y;
    const int qs = blockIdx.x * QT;
    const int t = threadIdx.x;
    const int qi = qs + t;

    const size_t head_off = (((size_t)b * NH + h) * SEQ) * HD;
    const float* qrow = g_q + head_off + (size_t)qi * HD;
    const float* kbase = g_k + head_off;
    const float* vbase = g_v + head_off;

    float4 q[16];
#pragma unroll
    for (int d4 = 0; d4 < 16; d4++) q[d4] = ((const float4*)qrow)[d4];

    const float slope = exp2f(-(float)(h + 1) * 0.5f);
    const int dmin = (qi < WIN) ? qi : WIN;

    float4 acc[16];
#pragma unroll
    for (int d4 = 0; d4 < 16; d4++) acc[d4] = make_float4(0.f, 0.f, 0.f, 0.f);
    float l = 0.f;

    const int lo = (qs >= WIN) ? (qs - WIN) : 0;

    for (int ck = lo; ck < qs + QT; ck += CK) {
        __syncthreads();
        const float4* ksrc = (const float4*)(kbase + (size_t)ck * HD);
        const float4* vsrc = (const float4*)(vbase + (size_t)ck * HD);
#pragma unroll
        for (int i = 0; i < 8; i++) {
            Ks[t + i * 128] = ksrc[t + i * 128];
            Vs[t + i * 128] = vsrc[t + i * 128];
        }
        __syncthreads();

        const float cc = slope * (float)(qi - dmin - ck);

#pragma unroll 1
        for (int j = 0; j < CK; j++) {
            int kv = ck + j;
            if (kv > qi || kv < qi - WIN) continue;

            float s0 = 0.f, s1 = 0.f, s2 = 0.f, s3 = 0.f;
#pragma unroll
            for (int d4 = 0; d4 < 16; d4 += 4) {
                float4 ka = Ks[j * 16 + d4 + 0];
                s0 = fmaf(q[d4 + 0].x, ka.x, s0); s0 = fmaf(q[d4 + 0].y, ka.y, s0);
                s0 = fmaf(q[d4 + 0].z, ka.z, s0); s0 = fmaf(q[d4 + 0].w, ka.w, s0);
                float4 kb = Ks[j * 16 + d4 + 1];
                s1 = fmaf(q[d4 + 1].x, kb.x, s1); s1 = fmaf(q[d4 + 1].y, kb.y, s1);
                s1 = fmaf(q[d4 + 1].z, kb.z, s1); s1 = fmaf(q[d4 + 1].w, kb.w, s1);
                float4 kc = Ks[j * 16 + d4 + 2];
                s2 = fmaf(q[d4 + 2].x, kc.x, s2); s2 = fmaf(q[d4 + 2].y, kc.y, s2);
                s2 = fmaf(q[d4 + 2].z, kc.z, s2); s2 = fmaf(q[d4 + 2].w, kc.w, s2);
                float4 kd = Ks[j * 16 + d4 + 3];
                s3 = fmaf(q[d4 + 3].x, kd.x, s3); s3 = fmaf(q[d4 + 3].y, kd.y, s3);
                s3 = fmaf(q[d4 + 3].z, kd.z, s3); s3 = fmaf(q[d4 + 3].w, kd.w, s3);
            }
            float s = (s0 + s1) + (s2 + s3);
            float arg = fmaf(s, 0.125f, fmaf(-slope, (float)j, cc));
            float p = __expf(arg);
            l += p;
#pragma unroll
            for (int d4 = 0; d4 < 16; d4++) {
                float4 vv = Vs[j * 16 + d4];
                acc[d4].x = fmaf(p, vv.x, acc[d4].x);
                acc[d4].y = fmaf(p, vv.y, acc[d4].y);
                acc[d4].z = fmaf(p, vv.z, acc[d4].z);
                acc[d4].w = fmaf(p, vv.w, acc[d4].w);
            }
        }
    }

    const float inv = 1.f / l;
    float* orow = g_o + ((size_t)b * SEQ + qi) * EMB + h * HD;
#pragma unroll
    for (int d4 = 0; d4 < 16; d4++) {
        float4 r = acc[d4];
        r.x *= inv; r.y *= inv; r.z *= inv; r.w *= inv;
        ((float4*)orow)[d4] = r;
    }
}

// ---------------------------------------------------------------------------
extern "C" void kernel_launch(void* const* d_in, const int* in_sizes, int n_in,
                              void* d_out, int out_size)
{
    const float* x     = (const float*)d_in[0];   // [B,S,E]
    const float* w_in  = (const float*)d_in[1];   // [3E,E]
    const float* w_out = (const float*)d_in[2];   // [E,E]
    float* out = (float*)d_out;                   // [B,S,E]

    float* go_ptr = nullptr;
    cudaGetSymbolAddress((void**)&go_ptr, g_o);

    // 1) QKV projection: [8192,3072] scattered to q/k/v [B,H,S,D]
    {
        dim3 grid(3 * EMB / BN, (BATCH * SEQ) / BM);
        qkv_gemm<<<grid, 256>>>(x, w_in);
    }
    // 2) Sliding-window attention -> g_o [B,S,E]
    {
        dim3 grid(SEQ / QT, NH, BATCH);
        attn_kernel<<<grid, 128>>>();
    }
    // 3) Output projection
    {
        dim3 grid(EMB / BN, (BATCH * SEQ) / BM);
        out_gemm<<<grid, 256>>>(go_ptr, w_out, out);
    }
}

// round 12
// speedup vs baseline: 2.0296x; 1.1426x over previous
#include <cuda_runtime.h>
#include <cuda_bf16.h>
#include <math.h>
#include <stdint.h>

// Problem constants
#define BATCH 4
#define SEQ   2048
#define EMB   1024
#define NH    16
#define HD    64
#define WIN   512

// Scratch (device globals; allocation is forbidden)
__device__ float g_q[(size_t)BATCH * NH * SEQ * HD];   // [B,H,S,D] fp32
__device__ float g_k[(size_t)BATCH * NH * SEQ * HD];
__device__ float g_v[(size_t)BATCH * NH * SEQ * HD];
// TF32 (pre-converted) operands for the tensor-core GEMMs
__device__ uint32_t g_xa[(size_t)BATCH * SEQ * EMB];   // x in tf32
__device__ uint32_t g_wi[(size_t)3 * EMB * EMB];       // w_in in tf32
__device__ uint32_t g_wo[(size_t)EMB * EMB];           // w_out in tf32
__device__ uint32_t g_ot[(size_t)BATCH * SEQ * EMB];   // attn out [B,S,E] in tf32

__device__ __forceinline__ uint32_t f2tf(float x) {
    uint32_t r;
    asm("cvt.rna.tf32.f32 %0, %1;" : "=r"(r) : "f"(x));
    return r;
}
__device__ __forceinline__ uint4 cvt4(float4 v) {
    return make_uint4(f2tf(v.x), f2tf(v.y), f2tf(v.z), f2tf(v.w));
}

// fp32 -> tf32 bulk converter (bandwidth-bound, ~few us each)
__global__ __launch_bounds__(256)
void to_tf32(const float* __restrict__ in, uint32_t* __restrict__ out, int n)
{
    int i = (blockIdx.x * blockDim.x + threadIdx.x) * 4;
    if (i < n) {
        float4 v = *(const float4*)(in + i);
        *(uint4*)(out + i) = cvt4(v);
    }
}

// ---------------------------------------------------------------------------
// TF32 tensor-core GEMM (NT): C[M,N] = A[M,K] * B[N,K]^T, K=1024.
// Inputs already tf32. Block tile 128x128, K-tile 16, 256 threads = 8 warps
// (4M x 2N), warp tile 32x64 via mma.sync m16n8k8.
// 3-stage cp.async pipeline: one __syncthreads per k-tile.
// Smem natural [row][k] layout; permuted k-assignment across the two
// k-slices (thread tg owns phys k {4tg..4tg+3}) — valid since A and B agree.
// ---------------------------------------------------------------------------
#define BM 128
#define BN 128
#define BKK 16
#define STG 3

#define MMA_TF32(c, a, b0_, b1_)                                            \
    asm volatile(                                                           \
        "mma.sync.aligned.m16n8k8.row.col.f32.tf32.tf32.f32 "               \
        "{%0,%1,%2,%3}, {%4,%5,%6,%7}, {%8,%9}, {%0,%1,%2,%3};"            \
        : "+f"((c)[0]), "+f"((c)[1]), "+f"((c)[2]), "+f"((c)[3])            \
        : "r"((a)[0]), "r"((a)[1]), "r"((a)[2]), "r"((a)[3]),               \
          "r"(b0_), "r"(b1_))

__device__ __forceinline__ void cp_async16(uint32_t saddr, const void* gptr) {
    asm volatile("cp.async.cg.shared.global [%0], [%1], 16;\n"
                 :: "r"(saddr), "l"(gptr));
}
#define CP_COMMIT() asm volatile("cp.async.commit_group;\n" ::: "memory")
#define CP_WAIT1()  asm volatile("cp.async.wait_group 1;\n" ::: "memory")

__device__ __forceinline__ void gemm_mainloop(
    const uint32_t* __restrict__ Ag, const uint32_t* __restrict__ Bg,
    uint32_t (*As)[BM][BKK], uint32_t (*Bs)[BN][BKK],
    float acc[2][8][4],
    int tid, int warpM, int warpN, int g, int tg)
{
    const int K = EMB;
    const int NT = K / BKK;          // 64 k-tiles
    const int r = tid >> 2;          // 0..63 (rows r, r+64)
    const int c = (tid & 3) << 2;    // 0,4,8,12

    const uint32_t* A0 = Ag + (size_t)r * K + c;
    const uint32_t* A1 = Ag + (size_t)(r + 64) * K + c;
    const uint32_t* B0 = Bg + (size_t)r * K + c;
    const uint32_t* B1 = Bg + (size_t)(r + 64) * K + c;

    uint32_t sa0[STG], sa1[STG], sb0[STG], sb1[STG];
#pragma unroll
    for (int s = 0; s < STG; s++) {
        sa0[s] = (uint32_t)__cvta_generic_to_shared(&As[s][r][c]);
        sa1[s] = (uint32_t)__cvta_generic_to_shared(&As[s][r + 64][c]);
        sb0[s] = (uint32_t)__cvta_generic_to_shared(&Bs[s][r][c]);
        sb1[s] = (uint32_t)__cvta_generic_to_shared(&Bs[s][r + 64][c]);
    }

    // prologue: tiles 0 and 1
    cp_async16(sa0[0], A0);      cp_async16(sa1[0], A1);
    cp_async16(sb0[0], B0);      cp_async16(sb1[0], B1);
    CP_COMMIT();
    cp_async16(sa0[1], A0 + BKK); cp_async16(sa1[1], A1 + BKK);
    cp_async16(sb0[1], B0 + BKK); cp_async16(sb1[1], B1 + BKK);
    CP_COMMIT();

    int st = 0;
    for (int kt = 0; kt < NT; kt++) {
        CP_WAIT1();              // tile kt resident
        __syncthreads();

        // issue tile kt+2 into the stage freed by compute kt-1
        if (kt + 2 < NT) {
            int sn = (st + 2 >= STG) ? st + 2 - STG : st + 2;
            int ko = (kt + 2) * BKK;
            cp_async16(sa0[sn], A0 + ko); cp_async16(sa1[sn], A1 + ko);
            cp_async16(sb0[sn], B0 + ko); cp_async16(sb1[sn], B1 + ko);
        }
        CP_COMMIT();             // one group per iteration (may be empty)

        // compute stage st
        uint32_t a[2][2][4];     // [ks][mt][frag]
#pragma unroll
        for (int mt = 0; mt < 2; mt++) {
            int row = warpM * 32 + mt * 16 + g;
            uint4 va = *(const uint4*)&As[st][row][tg * 4];
            uint4 vb = *(const uint4*)&As[st][row + 8][tg * 4];
            a[0][mt][0] = va.x; a[0][mt][1] = vb.x;
            a[0][mt][2] = va.y; a[0][mt][3] = vb.y;
            a[1][mt][0] = va.z; a[1][mt][1] = vb.z;
            a[1][mt][2] = va.w; a[1][mt][3] = vb.w;
        }
#pragma unroll
        for (int nt = 0; nt < 8; nt++) {
            int col = warpN * 64 + nt * 8 + g;
            uint4 wv = *(const uint4*)&Bs[st][col][tg * 4];
            MMA_TF32(acc[0][nt], a[0][0], wv.x, wv.y);
            MMA_TF32(acc[1][nt], a[0][1], wv.x, wv.y);
            MMA_TF32(acc[0][nt], a[1][0], wv.z, wv.w);
            MMA_TF32(acc[1][nt], a[1][1], wv.z, wv.w);
        }
        st = (st + 1 >= STG) ? 0 : st + 1;
    }
}

// GEMM1: qkv projection with scatter into g_q/g_k/g_v ([B,H,S,D] layout)
__global__ __launch_bounds__(256, 2)
void qkv_gemm(const uint32_t* __restrict__ A,    // x tf32   [8192, 1024]
              const uint32_t* __restrict__ B)    // w_in tf32 [3072, 1024]
{
    __shared__ uint32_t As[STG][BM][BKK];
    __shared__ uint32_t Bs[STG][BN][BKK];

    const int tid = threadIdx.x;
    const int m0 = blockIdx.y * BM;
    const int n0 = blockIdx.x * BN;
    const int warp = tid >> 5;
    const int warpM = warp >> 1;
    const int warpN = warp & 1;
    const int lane = tid & 31;
    const int g = lane >> 2;
    const int tg = lane & 3;

    float acc[2][8][4];
#pragma unroll
    for (int mt = 0; mt < 2; mt++)
#pragma unroll
        for (int nt = 0; nt < 8; nt++)
#pragma unroll
            for (int j = 0; j < 4; j++) acc[mt][nt][j] = 0.f;

    gemm_mainloop(A + (size_t)m0 * EMB, B + (size_t)n0 * EMB,
                  As, Bs, acc, tid, warpM, warpN, g, tg);

    // Scatter epilogue into q/k/v [B,H,S,D] (fp32)
#pragma unroll
    for (int nt = 0; nt < 8; nt++) {
        int f = n0 + warpN * 64 + nt * 8 + 2 * tg;
        int part = f >> 10;            // 0=q, 1=k, 2=v
        int e2 = f & 1023;
        int hh = e2 >> 6;
        int d0 = e2 & 63;
        float* base = (part == 0) ? g_q : (part == 1) ? g_k : g_v;
#pragma unroll
        for (int mt = 0; mt < 2; mt++) {
            int r0 = m0 + warpM * 32 + mt * 16 + g;
            {
                int bb = r0 >> 11;
                int ss = r0 & 2047;
                size_t off = ((((size_t)bb * NH + hh) * SEQ) + ss) * HD + d0;
                *(float2*)(base + off) = make_float2(acc[mt][nt][0], acc[mt][nt][1]);
            }
            {
                int r1 = r0 + 8;
                int bb = r1 >> 11;
                int ss = r1 & 2047;
                size_t off = ((((size_t)bb * NH + hh) * SEQ) + ss) * HD + d0;
                *(float2*)(base + off) = make_float2(acc[mt][nt][2], acc[mt][nt][3]);
            }
        }
    }
}

// GEMM2: output projection, plain row-major fp32 C
__global__ __launch_bounds__(256, 2)
void out_gemm(const uint32_t* __restrict__ A,    // g_ot tf32 [8192, 1024]
              const uint32_t* __restrict__ B,    // w_out tf32 [1024, 1024]
              float* __restrict__ C)             // out [8192, 1024]
{
    __shared__ uint32_t As[STG][BM][BKK];
    __shared__ uint32_t Bs[STG][BN][BKK];

    const int tid = threadIdx.x;
    const int m0 = blockIdx.y * BM;
    const int n0 = blockIdx.x * BN;
    const int warp = tid >> 5;
    const int warpM = warp >> 1;
    const int warpN = warp & 1;
    const int lane = tid & 31;
    const int g = lane >> 2;
    const int tg = lane & 3;

    float acc[2][8][4];
#pragma unroll
    for (int mt = 0; mt < 2; mt++)
#pragma unroll
        for (int nt = 0; nt < 8; nt++)
#pragma unroll
            for (int j = 0; j < 4; j++) acc[mt][nt][j] = 0.f;

    gemm_mainloop(A + (size_t)m0 * EMB, B + (size_t)n0 * EMB,
                  As, Bs, acc, tid, warpM, warpN, g, tg);

#pragma unroll
    for (int nt = 0; nt < 8; nt++) {
        int f = n0 + warpN * 64 + nt * 8 + 2 * tg;
#pragma unroll
        for (int mt = 0; mt < 2; mt++) {
            int r0 = m0 + warpM * 32 + mt * 16 + g;
            *(float2*)(C + (size_t)r0 * EMB + f) =
                make_float2(acc[mt][nt][0], acc[mt][nt][1]);
            *(float2*)(C + (size_t)(r0 + 8) * EMB + f) =
                make_float2(acc[mt][nt][2], acc[mt][nt][3]);
        }
    }
}

// ---------------------------------------------------------------------------
// Sliding-window attention with ALiBi. Grid: (S/128, H, B). 128 threads,
// one query per thread. Softmax shift is the analytic bound
// m = slope * min(qi, WIN). Output written directly as tf32 bits (g_ot).
// ---------------------------------------------------------------------------
#define QT 128
#define CK 64

__global__ __launch_bounds__(128)
void attn_kernel()
{
    __shared__ float4 Ks[CK * 16];
    __shared__ float4 Vs[CK * 16];

    const int b = blockIdx.z;
    const int h = blockIdx.y;
    const int qs = blockIdx.x * QT;
    const int t = threadIdx.x;
    const int qi = qs + t;

    const size_t head_off = (((size_t)b * NH + h) * SEQ) * HD;
    const float* qrow = g_q + head_off + (size_t)qi * HD;
    const float* kbase = g_k + head_off;
    const float* vbase = g_v + head_off;

    float4 q[16];
#pragma unroll
    for (int d4 = 0; d4 < 16; d4++) q[d4] = ((const float4*)qrow)[d4];

    const float slope = exp2f(-(float)(h + 1) * 0.5f);
    const int dmin = (qi < WIN) ? qi : WIN;

    float4 acc[16];
#pragma unroll
    for (int d4 = 0; d4 < 16; d4++) acc[d4] = make_float4(0.f, 0.f, 0.f, 0.f);
    float l = 0.f;

    const int lo = (qs >= WIN) ? (qs - WIN) : 0;

    for (int ck = lo; ck < qs + QT; ck += CK) {
        __syncthreads();
        const float4* ksrc = (const float4*)(kbase + (size_t)ck * HD);
        const float4* vsrc = (const float4*)(vbase + (size_t)ck * HD);
#pragma unroll
        for (int i = 0; i < 8; i++) {
            Ks[t + i * 128] = ksrc[t + i * 128];
            Vs[t + i * 128] = vsrc[t + i * 128];
        }
        __syncthreads();

        const float cc = slope * (float)(qi - dmin - ck);

#pragma unroll 1
        for (int j = 0; j < CK; j++) {
            int kv = ck + j;
            if (kv > qi || kv < qi - WIN) continue;

            float s0 = 0.f, s1 = 0.f, s2 = 0.f, s3 = 0.f;
#pragma unroll
            for (int d4 = 0; d4 < 16; d4 += 4) {
                float4 ka = Ks[j * 16 + d4 + 0];
                s0 = fmaf(q[d4 + 0].x, ka.x, s0); s0 = fmaf(q[d4 + 0].y, ka.y, s0);
                s0 = fmaf(q[d4 + 0].z, ka.z, s0); s0 = fmaf(q[d4 + 0].w, ka.w, s0);
                float4 kb = Ks[j * 16 + d4 + 1];
                s1 = fmaf(q[d4 + 1].x, kb.x, s1); s1 = fmaf(q[d4 + 1].y, kb.y, s1);
                s1 = fmaf(q[d4 + 1].z, kb.z, s1); s1 = fmaf(q[d4 + 1].w, kb.w, s1);
                float4 kc = Ks[j * 16 + d4 + 2];
                s2 = fmaf(q[d4 + 2].x, kc.x, s2); s2 = fmaf(q[d4 + 2].y, kc.y, s2);
                s2 = fmaf(q[d4 + 2].z, kc.z, s2); s2 = fmaf(q[d4 + 2].w, kc.w, s2);
                float4 kd = Ks[j * 16 + d4 + 3];
                s3 = fmaf(q[d4 + 3].x, kd.x, s3); s3 = fmaf(q[d4 + 3].y, kd.y, s3);
                s3 = fmaf(q[d4 + 3].z, kd.z, s3); s3 = fmaf(q[d4 + 3].w, kd.w, s3);
            }
            float s = (s0 + s1) + (s2 + s3);
            float arg = fmaf(s, 0.125f, fmaf(-slope, (float)j, cc));
            float p = __expf(arg);
            l += p;
#pragma unroll
            for (int d4 = 0; d4 < 16; d4++) {
                float4 vv = Vs[j * 16 + d4];
                acc[d4].x = fmaf(p, vv.x, acc[d4].x);
                acc[d4].y = fmaf(p, vv.y, acc[d4].y);
                acc[d4].z = fmaf(p, vv.z, acc[d4].z);
                acc[d4].w = fmaf(p, vv.w, acc[d4].w);
            }
        }
    }

    const float inv = 1.f / l;
    uint32_t* orow = g_ot + ((size_t)b * SEQ + qi) * EMB + h * HD;
#pragma unroll
    for (int d4 = 0; d4 < 16; d4++) {
        float4 r = acc[d4];
        r.x *= inv; r.y *= inv; r.z *= inv; r.w *= inv;
        ((uint4*)orow)[d4] = cvt4(r);
    }
}

// ---------------------------------------------------------------------------
extern "C" void kernel_launch(void* const* d_in, const int* in_sizes, int n_in,
                              void* d_out, int out_size)
{
    const float* x     = (const float*)d_in[0];   // [B,S,E]
    const float* w_in  = (const float*)d_in[1];   // [3E,E]
    const float* w_out = (const float*)d_in[2];   // [E,E]
    float* out = (float*)d_out;                   // [B,S,E]

    uint32_t *xa, *wi, *wo, *ot;
    cudaGetSymbolAddress((void**)&xa, g_xa);
    cudaGetSymbolAddress((void**)&wi, g_wi);
    cudaGetSymbolAddress((void**)&wo, g_wo);
    cudaGetSymbolAddress((void**)&ot, g_ot);

    // 0) one-shot tf32 conversions (bandwidth-bound)
    {
        int nx = BATCH * SEQ * EMB;         // 8M
        int ni = 3 * EMB * EMB;             // 3M
        int no = EMB * EMB;                 // 1M
        to_tf32<<<nx / 1024, 256>>>(x, xa, nx);
        to_tf32<<<ni / 1024, 256>>>(w_in, wi, ni);
        to_tf32<<<no / 1024, 256>>>(w_out, wo, no);
    }
    // 1) QKV projection: [8192,3072] scattered to q/k/v [B,H,S,D]
    {
        dim3 grid(3 * EMB / BN, (BATCH * SEQ) / BM);
        qkv_gemm<<<grid, 256>>>(xa, wi);
    }
    // 2) Sliding-window attention -> g_ot [B,S,E] (tf32)
    {
        dim3 grid(SEQ / QT, NH, BATCH);
        attn_kernel<<<grid, 128>>>();
    }
    // 3) Output projection
    {
        dim3 grid(EMB / BN, (BATCH * SEQ) / BM);
        out_gemm<<<grid, 256>>>(ot, wo, out);
    }
}

// round 13
// speedup vs baseline: 3.4454x; 1.6976x over previous
#include <cuda_runtime.h>
#include <cuda_bf16.h>
#include <math.h>
#include <stdint.h>

// Problem constants
#define BATCH 4
#define SEQ   2048
#define EMB   1024
#define NH    16
#define HD    64
#define WIN   512

// Scratch (device globals; allocation is forbidden).
// q/k/v are stored as TF32 bit patterns (uint32) — produced by qkv_gemm
// epilogue, consumed directly by the tensor-core attention.
__device__ uint32_t g_q[(size_t)BATCH * NH * SEQ * HD];   // [B,H,S,D] tf32
__device__ uint32_t g_k[(size_t)BATCH * NH * SEQ * HD];
__device__ uint32_t g_v[(size_t)BATCH * NH * SEQ * HD];
__device__ uint32_t g_xa[(size_t)BATCH * SEQ * EMB];      // x in tf32
__device__ uint32_t g_wi[(size_t)3 * EMB * EMB];          // w_in in tf32
__device__ uint32_t g_wo[(size_t)EMB * EMB];              // w_out in tf32
__device__ uint32_t g_ot[(size_t)BATCH * SEQ * EMB];      // attn out [B,S,E] tf32

__device__ __forceinline__ uint32_t f2tf(float x) {
    uint32_t r;
    asm("cvt.rna.tf32.f32 %0, %1;" : "=r"(r) : "f"(x));
    return r;
}
__device__ __forceinline__ uint4 cvt4(float4 v) {
    return make_uint4(f2tf(v.x), f2tf(v.y), f2tf(v.z), f2tf(v.w));
}

// fp32 -> tf32 bulk converter
__global__ __launch_bounds__(256)
void to_tf32(const float* __restrict__ in, uint32_t* __restrict__ out, int n)
{
    int i = (blockIdx.x * blockDim.x + threadIdx.x) * 4;
    if (i < n) {
        float4 v = *(const float4*)(in + i);
        *(uint4*)(out + i) = cvt4(v);
    }
}

#define MMA_TF32(c, a, b0_, b1_)                                            \
    asm volatile(                                                           \
        "mma.sync.aligned.m16n8k8.row.col.f32.tf32.tf32.f32 "               \
        "{%0,%1,%2,%3}, {%4,%5,%6,%7}, {%8,%9}, {%0,%1,%2,%3};"            \
        : "+f"((c)[0]), "+f"((c)[1]), "+f"((c)[2]), "+f"((c)[3])            \
        : "r"((a)[0]), "r"((a)[1]), "r"((a)[2]), "r"((a)[3]),               \
          "r"(b0_), "r"(b1_))

// ---------------------------------------------------------------------------
// TF32 tensor-core GEMM (NT): C[M,N] = A[M,K] * B[N,K]^T, K=1024.
// Block tile 128x128, K-tile 16, 256 threads = 8 warps (4M x 2N),
// warp tile 32x64. 3-stage cp.async pipeline.
// ---------------------------------------------------------------------------
#define BM 128
#define BN 128
#define BKK 16
#define STG 3

__device__ __forceinline__ void cp_async16(uint32_t saddr, const void* gptr) {
    asm volatile("cp.async.cg.shared.global [%0], [%1], 16;\n"
                 :: "r"(saddr), "l"(gptr));
}
#define CP_COMMIT() asm volatile("cp.async.commit_group;\n" ::: "memory")
#define CP_WAIT1()  asm volatile("cp.async.wait_group 1;\n" ::: "memory")

__device__ __forceinline__ void gemm_mainloop(
    const uint32_t* __restrict__ Ag, const uint32_t* __restrict__ Bg,
    uint32_t (*As)[BM][BKK], uint32_t (*Bs)[BN][BKK],
    float acc[2][8][4],
    int tid, int warpM, int warpN, int g, int tg)
{
    const int K = EMB;
    const int NT = K / BKK;
    const int r = tid >> 2;
    const int c = (tid & 3) << 2;

    const uint32_t* A0 = Ag + (size_t)r * K + c;
    const uint32_t* A1 = Ag + (size_t)(r + 64) * K + c;
    const uint32_t* B0 = Bg + (size_t)r * K + c;
    const uint32_t* B1 = Bg + (size_t)(r + 64) * K + c;

    uint32_t sa0[STG], sa1[STG], sb0[STG], sb1[STG];
#pragma unroll
    for (int s = 0; s < STG; s++) {
        sa0[s] = (uint32_t)__cvta_generic_to_shared(&As[s][r][c]);
        sa1[s] = (uint32_t)__cvta_generic_to_shared(&As[s][r + 64][c]);
        sb0[s] = (uint32_t)__cvta_generic_to_shared(&Bs[s][r][c]);
        sb1[s] = (uint32_t)__cvta_generic_to_shared(&Bs[s][r + 64][c]);
    }

    cp_async16(sa0[0], A0);       cp_async16(sa1[0], A1);
    cp_async16(sb0[0], B0);       cp_async16(sb1[0], B1);
    CP_COMMIT();
    cp_async16(sa0[1], A0 + BKK); cp_async16(sa1[1], A1 + BKK);
    cp_async16(sb0[1], B0 + BKK); cp_async16(sb1[1], B1 + BKK);
    CP_COMMIT();

    int st = 0;
    for (int kt = 0; kt < NT; kt++) {
        CP_WAIT1();
        __syncthreads();

        if (kt + 2 < NT) {
            int sn = (st + 2 >= STG) ? st + 2 - STG : st + 2;
            int ko = (kt + 2) * BKK;
            cp_async16(sa0[sn], A0 + ko); cp_async16(sa1[sn], A1 + ko);
            cp_async16(sb0[sn], B0 + ko); cp_async16(sb1[sn], B1 + ko);
        }
        CP_COMMIT();

        uint32_t a[2][2][4];
#pragma unroll
        for (int mt = 0; mt < 2; mt++) {
            int row = warpM * 32 + mt * 16 + g;
            uint4 va = *(const uint4*)&As[st][row][tg * 4];
            uint4 vb = *(const uint4*)&As[st][row + 8][tg * 4];
            a[0][mt][0] = va.x; a[0][mt][1] = vb.x;
            a[0][mt][2] = va.y; a[0][mt][3] = vb.y;
            a[1][mt][0] = va.z; a[1][mt][1] = vb.z;
            a[1][mt][2] = va.w; a[1][mt][3] = vb.w;
        }
#pragma unroll
        for (int nt = 0; nt < 8; nt++) {
            int col = warpN * 64 + nt * 8 + g;
            uint4 wv = *(const uint4*)&Bs[st][col][tg * 4];
            MMA_TF32(acc[0][nt], a[0][0], wv.x, wv.y);
            MMA_TF32(acc[1][nt], a[0][1], wv.x, wv.y);
            MMA_TF32(acc[0][nt], a[1][0], wv.z, wv.w);
            MMA_TF32(acc[1][nt], a[1][1], wv.z, wv.w);
        }
        st = (st + 1 >= STG) ? 0 : st + 1;
    }
}

// GEMM1: qkv projection; scatter tf32 bits into g_q/g_k/g_v ([B,H,S,D])
__global__ __launch_bounds__(256, 2)
void qkv_gemm(const uint32_t* __restrict__ A,
              const uint32_t* __restrict__ B)
{
    __shared__ uint32_t As[STG][BM][BKK];
    __shared__ uint32_t Bs[STG][BN][BKK];

    const int tid = threadIdx.x;
    const int m0 = blockIdx.y * BM;
    const int n0 = blockIdx.x * BN;
    const int warp = tid >> 5;
    const int warpM = warp >> 1;
    const int warpN = warp & 1;
    const int lane = tid & 31;
    const int g = lane >> 2;
    const int tg = lane & 3;

    float acc[2][8][4];
#pragma unroll
    for (int mt = 0; mt < 2; mt++)
#pragma unroll
        for (int nt = 0; nt < 8; nt++)
#pragma unroll
            for (int j = 0; j < 4; j++) acc[mt][nt][j] = 0.f;

    gemm_mainloop(A + (size_t)m0 * EMB, B + (size_t)n0 * EMB,
                  As, Bs, acc, tid, warpM, warpN, g, tg);

#pragma unroll
    for (int nt = 0; nt < 8; nt++) {
        int f = n0 + warpN * 64 + nt * 8 + 2 * tg;
        int part = f >> 10;
        int e2 = f & 1023;
        int hh = e2 >> 6;
        int d0 = e2 & 63;
        uint32_t* base = (part == 0) ? g_q : (part == 1) ? g_k : g_v;
#pragma unroll
        for (int mt = 0; mt < 2; mt++) {
            int r0 = m0 + warpM * 32 + mt * 16 + g;
            {
                int bb = r0 >> 11;
                int ss = r0 & 2047;
                size_t off = ((((size_t)bb * NH + hh) * SEQ) + ss) * HD + d0;
                *(uint2*)(base + off) =
                    make_uint2(f2tf(acc[mt][nt][0]), f2tf(acc[mt][nt][1]));
            }
            {
                int r1 = r0 + 8;
                int bb = r1 >> 11;
                int ss = r1 & 2047;
                size_t off = ((((size_t)bb * NH + hh) * SEQ) + ss) * HD + d0;
                *(uint2*)(base + off) =
                    make_uint2(f2tf(acc[mt][nt][2]), f2tf(acc[mt][nt][3]));
            }
        }
    }
}

// GEMM2: output projection, plain row-major fp32 C
__global__ __launch_bounds__(256, 2)
void out_gemm(const uint32_t* __restrict__ A,
              const uint32_t* __restrict__ B,
              float* __restrict__ C)
{
    __shared__ uint32_t As[STG][BM][BKK];
    __shared__ uint32_t Bs[STG][BN][BKK];

    const int tid = threadIdx.x;
    const int m0 = blockIdx.y * BM;
    const int n0 = blockIdx.x * BN;
    const int warp = tid >> 5;
    const int warpM = warp >> 1;
    const int warpN = warp & 1;
    const int lane = tid & 31;
    const int g = lane >> 2;
    const int tg = lane & 3;

    float acc[2][8][4];
#pragma unroll
    for (int mt = 0; mt < 2; mt++)
#pragma unroll
        for (int nt = 0; nt < 8; nt++)
#pragma unroll
            for (int j = 0; j < 4; j++) acc[mt][nt][j] = 0.f;

    gemm_mainloop(A + (size_t)m0 * EMB, B + (size_t)n0 * EMB,
                  As, Bs, acc, tid, warpM, warpN, g, tg);

#pragma unroll
    for (int nt = 0; nt < 8; nt++) {
        int f = n0 + warpN * 64 + nt * 8 + 2 * tg;
#pragma unroll
        for (int mt = 0; mt < 2; mt++) {
            int r0 = m0 + warpM * 32 + mt * 16 + g;
            *(float2*)(C + (size_t)r0 * EMB + f) =
                make_float2(acc[mt][nt][0], acc[mt][nt][1]);
            *(float2*)(C + (size_t)(r0 + 8) * EMB + f) =
                make_float2(acc[mt][nt][2], acc[mt][nt][3]);
        }
    }
}

// ---------------------------------------------------------------------------
// Tensor-core sliding-window attention with ALiBi.
// Grid (S/128, H, B), 256 threads = 8 warps; warp w owns q rows [16w,16w+16).
// KV tiles of 64. Q kept in registers for the whole CTA. Fixed analytic
// softmax shift (slope*min(qi,WIN)) -> no online max, no rescaling; O and l
// accumulate across tiles, one divide at the end.
// Smem tiles use chunk-XOR swizzle: word = row*64 + 4*(chunk ^ ((row&3)<<2)).
// All LDS.128 / STS.128 patterns conflict-free; P stores 2-way.
// ---------------------------------------------------------------------------
#define AQT 128
#define AKT 64

__device__ __forceinline__ int swz(int row, int chunk) {
    return (row << 6) + (((chunk) ^ ((row & 3) << 2)) << 2);
}

__global__ __launch_bounds__(256, 2)
void attn_tc()
{
    extern __shared__ uint32_t sm[];
    uint32_t* Ks = sm;             // [64][64] swizzled (kv-major)
    uint32_t* Vt = sm + 4096;      // [64][64] swizzled (d-major, transposed V)
    uint32_t* Ps = sm + 8192;      // [128][64] swizzled (per-warp 16-row slices)

    const int b = blockIdx.z, h = blockIdx.y;
    const int qs = blockIdx.x * AQT;
    const int t = threadIdx.x;
    const int w = t >> 5, lane = t & 31;
    const int g = lane >> 2, tg = lane & 3;
    const int wr = w * 16;

    const size_t head_off = (((size_t)b * NH + h) * SEQ) * HD;
    const uint32_t* Qg = g_q + head_off;
    const uint32_t* Kg = g_k + head_off;
    const uint32_t* Vg = g_v + head_off;

    // Q fragments (held in registers for entire CTA): rows wr+g, wr+8+g
    uint4 qv[2][4];
    {
        const uint32_t* q0 = Qg + (size_t)(qs + wr + g) * HD + 4 * tg;
        const uint32_t* q1 = Qg + (size_t)(qs + wr + 8 + g) * HD + 4 * tg;
#pragma unroll
        for (int i = 0; i < 4; i++) {
            qv[0][i] = *(const uint4*)(q0 + 16 * i);
            qv[1][i] = *(const uint4*)(q1 + 16 * i);
        }
    }

    const float slope = exp2f(-(float)(h + 1) * 0.5f);
    const int row0 = qs + wr + g, row1 = row0 + 8;
    const float sh0 = slope * (float)((row0 < WIN) ? row0 : WIN);
    const float sh1 = slope * (float)((row1 < WIN) ? row1 : WIN);

    float oacc[8][4];
#pragma unroll
    for (int nt = 0; nt < 8; nt++)
#pragma unroll
        for (int j = 0; j < 4; j++) oacc[nt][j] = 0.f;
    float l0 = 0.f, l1 = 0.f;

    const int lo = (qs >= WIN) ? qs - WIN : 0;
    const int krow = t >> 2, kq = t & 3;       // K loader mapping
    const int vkv = t & 63, vdb = t >> 6;      // V loader mapping

    for (int kb = lo; kb < qs + AQT; kb += AKT) {
        __syncthreads();   // previous tile fully consumed
        // load K tile [64 kv][64 d]
        {
            const uint32_t* kg = Kg + (size_t)(kb + krow) * HD;
#pragma unroll
            for (int j = 0; j < 4; j++) {
                int c = kq + 4 * j;
                *(uint4*)&Ks[swz(krow, c)] = *(const uint4*)(kg + 4 * c);
            }
        }
        // load V tile transposed -> Vt[d][kv]
        {
            const uint32_t* vg = Vg + (size_t)(kb + vkv) * HD + vdb * 16;
#pragma unroll
            for (int j = 0; j < 4; j++) {
                uint4 val = *(const uint4*)(vg + 4 * j);
                int d0 = vdb * 16 + 4 * j;
                int cch = vkv >> 2, co = vkv & 3;
                Vt[swz(d0 + 0, cch) + co] = val.x;
                Vt[swz(d0 + 1, cch) + co] = val.y;
                Vt[swz(d0 + 2, cch) + co] = val.z;
                Vt[swz(d0 + 3, cch) + co] = val.w;
            }
        }
        __syncthreads();

        // scores: S[16][64] = Q @ K^T
        float sacc[8][4];
#pragma unroll
        for (int nt = 0; nt < 8; nt++)
#pragma unroll
            for (int j = 0; j < 4; j++) sacc[nt][j] = 0.f;
#pragma unroll
        for (int i = 0; i < 4; i++) {
            uint32_t ae[4] = {qv[0][i].x, qv[1][i].x, qv[0][i].y, qv[1][i].y};
            uint32_t ao[4] = {qv[0][i].z, qv[1][i].z, qv[0][i].w, qv[1][i].w};
#pragma unroll
            for (int nt = 0; nt < 8; nt++) {
                uint4 kvv = *(const uint4*)&Ks[swz(nt * 8 + g, tg + 4 * i)];
                MMA_TF32(sacc[nt], ae, kvv.x, kvv.y);
                MMA_TF32(sacc[nt], ao, kvv.z, kvv.w);
            }
        }

        // softmax (fixed shift) + stage P (tf32) into Ps
        const float b0c = slope * (float)(row0 - kb) - sh0;
        const float b1c = slope * (float)(row1 - kb) - sh1;
        const int pr0 = wr + g, pr1 = wr + 8 + g;
#pragma unroll
        for (int nt = 0; nt < 8; nt++) {
            int j0 = nt * 8 + 2 * tg;
            int d00 = row0 - (kb + j0);       // delta at col j0
            int d10 = row1 - (kb + j0);
            float a00 = fmaf(sacc[nt][0], 0.125f, fmaf(-slope, (float)j0, b0c));
            float a01 = fmaf(sacc[nt][1], 0.125f, fmaf(-slope, (float)(j0 + 1), b0c));
            float a10 = fmaf(sacc[nt][2], 0.125f, fmaf(-slope, (float)j0, b1c));
            float a11 = fmaf(sacc[nt][3], 0.125f, fmaf(-slope, (float)(j0 + 1), b1c));
            uint32_t p00 = (d00 >= 0 && d00 <= WIN) ? f2tf(__expf(a00)) : 0u;
            uint32_t p01 = (d00 >= 1 && d00 <= WIN + 1) ? f2tf(__expf(a01)) : 0u;
            uint32_t p10 = (d10 >= 0 && d10 <= WIN) ? f2tf(__expf(a10)) : 0u;
            uint32_t p11 = (d10 >= 1 && d10 <= WIN + 1) ? f2tf(__expf(a11)) : 0u;
            l0 += __uint_as_float(p00) + __uint_as_float(p01);
            l1 += __uint_as_float(p10) + __uint_as_float(p11);
            int ch = j0 >> 2, wo = j0 & 3;
            uint32_t* s0 = &Ps[swz(pr0, ch) + wo];
            s0[0] = p00; s0[1] = p01;
            uint32_t* s1 = &Ps[swz(pr1, ch) + wo];
            s1[0] = p10; s1[1] = p11;
        }
        __syncwarp();

        // O += P @ V  (A from Ps own-warp rows, B from Vt)
#pragma unroll
        for (int i = 0; i < 4; i++) {
            uint4 pa0 = *(const uint4*)&Ps[swz(pr0, tg + 4 * i)];
            uint4 pa1 = *(const uint4*)&Ps[swz(pr1, tg + 4 * i)];
            uint32_t ae[4] = {pa0.x, pa1.x, pa0.y, pa1.y};
            uint32_t ao[4] = {pa0.z, pa1.z, pa0.w, pa1.w};
#pragma unroll
            for (int nt = 0; nt < 8; nt++) {
                uint4 vv = *(const uint4*)&Vt[swz(nt * 8 + g, tg + 4 * i)];
                MMA_TF32(oacc[nt], ae, vv.x, vv.y);
                MMA_TF32(oacc[nt], ao, vv.z, vv.w);
            }
        }
    }

    // row sums across the 4-lane tg group, then normalize and write tf32
    l0 += __shfl_xor_sync(0xffffffffu, l0, 1);
    l0 += __shfl_xor_sync(0xffffffffu, l0, 2);
    l1 += __shfl_xor_sync(0xffffffffu, l1, 1);
    l1 += __shfl_xor_sync(0xffffffffu, l1, 2);
    const float inv0 = 1.f / l0, inv1 = 1.f / l1;

    uint32_t* o0 = g_ot + ((size_t)b * SEQ + row0) * EMB + h * HD;
    uint32_t* o1 = g_ot + ((size_t)b * SEQ + row1) * EMB + h * HD;
#pragma unroll
    for (int nt = 0; nt < 8; nt++) {
        int col = nt * 8 + 2 * tg;
        *(uint2*)(o0 + col) = make_uint2(f2tf(oacc[nt][0] * inv0),
                                         f2tf(oacc[nt][1] * inv0));
        *(uint2*)(o1 + col) = make_uint2(f2tf(oacc[nt][2] * inv1),
                                         f2tf(oacc[nt][3] * inv1));
    }
}

// ---------------------------------------------------------------------------
extern "C" void kernel_launch(void* const* d_in, const int* in_sizes, int n_in,
                              void* d_out, int out_size)
{
    const float* x     = (const float*)d_in[0];   // [B,S,E]
    const float* w_in  = (const float*)d_in[1];   // [3E,E]
    const float* w_out = (const float*)d_in[2];   // [E,E]
    float* out = (float*)d_out;                   // [B,S,E]

    uint32_t *xa, *wi, *wo, *ot;
    cudaGetSymbolAddress((void**)&xa, g_xa);
    cudaGetSymbolAddress((void**)&wi, g_wi);
    cudaGetSymbolAddress((void**)&wo, g_wo);
    cudaGetSymbolAddress((void**)&ot, g_ot);

    static bool attr_set = false;
    if (!attr_set) {
        cudaFuncSetAttribute(attn_tc,
                             cudaFuncAttributeMaxDynamicSharedMemorySize,
                             65536);
        attr_set = true;
    }

    // 0) one-shot tf32 conversions
    {
        int nx = BATCH * SEQ * EMB;
        int ni = 3 * EMB * EMB;
        int no = EMB * EMB;
        to_tf32<<<nx / 1024, 256>>>(x, xa, nx);
        to_tf32<<<ni / 1024, 256>>>(w_in, wi, ni);
        to_tf32<<<no / 1024, 256>>>(w_out, wo, no);
    }
    // 1) QKV projection -> q/k/v [B,H,S,D] tf32
    {
        dim3 grid(3 * EMB / BN, (BATCH * SEQ) / BM);
        qkv_gemm<<<grid, 256>>>(xa, wi);
    }
    // 2) tensor-core sliding-window attention -> g_ot [B,S,E] tf32
    {
        dim3 grid(SEQ / AQT, NH, BATCH);
        attn_tc<<<grid, 256, 65536>>>();
    }
    // 3) Output projection
    {
        dim3 grid(EMB / BN, (BATCH * SEQ) / BM);
        out_gemm<<<grid, 256>>>(ot, wo, out);
    }
}